// round 2
// baseline (speedup 1.0000x reference)
#include <cuda_runtime.h>
#include <cstdint>

// scatter-mean, dim=0:
//   src:   [E=800000, D=64] f32
//   index: [E] int64 (int32 if JAX x64 disabled — detected at runtime)
//   out:   [N=50000, D=64] f32
//
// Strategy: counting sort by segment, then one warp per segment gathers its
// rows (coalesced 256B each) and reduces in registers. No fp atomics at all.

#define D_DIM 64
#define N_SEG 50000
#define E_MAX 800000
#define SCAN_T 1024
#define SCAN_CHUNK ((N_SEG + SCAN_T - 1) / SCAN_T)   // 49

__device__ int g_is64;
__device__ int g_counts[N_SEG];
__device__ int g_offsets[N_SEG + 1];
__device__ int g_pos[N_SEG];
__device__ int g_perm[E_MAX];

// ---------------------------------------------------------------------------
// 1-warp index-dtype detection. Reading int32 data as int64 packs two random
// indices per word; hi half nonzero => value outside [0, N_SEG).
// Misdetect probability ~ (1/50000)^32.
// ---------------------------------------------------------------------------
__global__ void k_detect(const void* __restrict__ idxp) {
    const long long* p = (const long long*)idxp;
    long long v = p[threadIdx.x];
    unsigned ok = __ballot_sync(0xFFFFFFFFu, v >= 0 && v < (long long)N_SEG);
    if (threadIdx.x == 0) g_is64 = (ok == 0xFFFFFFFFu) ? 1 : 0;
}

__global__ void k_zero_counts() {
    int t = blockIdx.x * blockDim.x + threadIdx.x;
    if (t < N_SEG) g_counts[t] = 0;
}

__device__ __forceinline__ int load_idx(const void* idxp, int e, int is64) {
    return is64 ? (int)((const long long*)idxp)[e] : ((const int*)idxp)[e];
}

// ---------------------------------------------------------------------------
// Histogram of segment ids. 800K int atomics over 50K random bins — cheap.
// ---------------------------------------------------------------------------
__global__ void __launch_bounds__(256) k_hist(const void* __restrict__ idxp, int E) {
    int e = blockIdx.x * blockDim.x + threadIdx.x;
    if (e >= E) return;
    atomicAdd(&g_counts[load_idx(idxp, e, g_is64)], 1);
}

// ---------------------------------------------------------------------------
// Single-block exclusive scan over 50K bins. Each thread owns a 49-bin chunk:
// serial chunk sum -> Hillis-Steele over 1024 thread sums -> serial rewrite.
// Writes both g_offsets (stable) and g_pos (running cursor for permute).
// ---------------------------------------------------------------------------
__global__ void __launch_bounds__(SCAN_T) k_scan() {
    __shared__ int ssum[SCAN_T];
    int t = threadIdx.x;
    int base = t * SCAN_CHUNK;

    int sum = 0;
    for (int i = 0; i < SCAN_CHUNK; i++) {
        int j = base + i;
        if (j < N_SEG) sum += g_counts[j];
    }
    ssum[t] = sum;
    __syncthreads();

    for (int off = 1; off < SCAN_T; off <<= 1) {
        int v = (t >= off) ? ssum[t - off] : 0;
        __syncthreads();
        ssum[t] += v;
        __syncthreads();
    }

    int run = (t > 0) ? ssum[t - 1] : 0;   // exclusive prefix of this chunk
    for (int i = 0; i < SCAN_CHUNK; i++) {
        int j = base + i;
        if (j < N_SEG) {
            g_offsets[j] = run;
            g_pos[j]     = run;
            run += g_counts[j];
        }
    }
    if (t == SCAN_T - 1) g_offsets[N_SEG] = run;
}

// ---------------------------------------------------------------------------
// Build permutation: row e goes to slot atomicAdd(pos[idx]). Slot order within
// a segment is atomic-race order (fp sum order varies run-to-run, same as any
// atomic scatter — well inside the 1e-3 tolerance).
// ---------------------------------------------------------------------------
__global__ void __launch_bounds__(256) k_permute(const void* __restrict__ idxp, int E) {
    int e = blockIdx.x * blockDim.x + threadIdx.x;
    if (e >= E) return;
    int idx = load_idx(idxp, e, g_is64);
    int p = atomicAdd(&g_pos[idx], 1);
    g_perm[p] = e;
}

// ---------------------------------------------------------------------------
// Gather-reduce: one warp per segment. Lane owns a float2 column pair; a row
// load is 32 lanes x 8B = 256B fully coalesced. Unroll-4 over rows for MLP.
// Writes the normalized mean directly (no memset, no norm pass needed).
// ---------------------------------------------------------------------------
__global__ void __launch_bounds__(256) k_reduce(const float2* __restrict__ src2,
                                                float2* __restrict__ out2,
                                                int n_seg) {
    int warp = (blockIdx.x * blockDim.x + threadIdx.x) >> 5;
    int lane = threadIdx.x & 31;
    if (warp >= n_seg) return;

    int start = g_offsets[warp];
    int end   = g_offsets[warp + 1];
    int count = end - start;

    float2 a0 = {0.f, 0.f}, a1 = {0.f, 0.f}, a2 = {0.f, 0.f}, a3 = {0.f, 0.f};

    int r = start;
    for (; r + 4 <= end; r += 4) {
        int e0 = g_perm[r + 0];
        int e1 = g_perm[r + 1];
        int e2 = g_perm[r + 2];
        int e3 = g_perm[r + 3];
        float2 v0 = src2[e0 * 32 + lane];
        float2 v1 = src2[e1 * 32 + lane];
        float2 v2 = src2[e2 * 32 + lane];
        float2 v3 = src2[e3 * 32 + lane];
        a0.x += v0.x; a0.y += v0.y;
        a1.x += v1.x; a1.y += v1.y;
        a2.x += v2.x; a2.y += v2.y;
        a3.x += v3.x; a3.y += v3.y;
    }
    for (; r < end; r++) {
        int e = g_perm[r];
        float2 v = src2[e * 32 + lane];
        a0.x += v.x; a0.y += v.y;
    }

    float sx = (a0.x + a1.x) + (a2.x + a3.x);
    float sy = (a0.y + a1.y) + (a2.y + a3.y);
    float inv = 1.0f / (float)max(count, 1);

    float2 o; o.x = sx * inv; o.y = sy * inv;
    out2[warp * 32 + lane] = o;
}

// ---------------------------------------------------------------------------
extern "C" void kernel_launch(void* const* d_in, const int* in_sizes, int n_in,
                              void* d_out, int out_size) {
    const float* src  = (const float*)d_in[0];
    const void*  idxp = d_in[1];

    const int E     = in_sizes[0] / D_DIM;   // 800000
    const int rowsN = out_size / D_DIM;      // 50000

    k_detect<<<1, 32>>>(idxp);
    k_zero_counts<<<(N_SEG + 255) / 256, 256>>>();
    k_hist<<<(E + 255) / 256, 256>>>(idxp, E);
    k_scan<<<1, SCAN_T>>>();
    k_permute<<<(E + 255) / 256, 256>>>(idxp, E);

    int warps_needed = rowsN;                        // one warp per segment
    int blocks = (warps_needed * 32 + 255) / 256;
    k_reduce<<<blocks, 256>>>((const float2*)src, (float2*)d_out, rowsN);
}

// round 3
// speedup vs baseline: 1.9604x; 1.9604x over previous
#include <cuda_runtime.h>
#include <cstdint>

// scatter-mean dim=0: src [E=800000, D=64] f32, index [E] i64/i32, out [N=50000, D=64] f32
// Counting-sort by segment + warp-per-segment gather-reduce. No fp atomics.

#define D_DIM   64
#define N_SEG   50000
#define E_MAX   800000
#define SCAN_T  1024
#define SCAN_B  ((N_SEG + SCAN_T - 1) / SCAN_T)     // 49 blocks

__device__ int g_is64;
__device__ int g_counts[N_SEG];
__device__ int g_offsets[N_SEG + 1];
__device__ int g_pos[N_SEG];
__device__ int g_perm[E_MAX];
__device__ int g_bsum[SCAN_B];

__device__ __forceinline__ int load_idx(const void* idxp, int e, int is64) {
    return is64 ? (int)((const long long*)idxp)[e] : ((const int*)idxp)[e];
}

// ---------------------------------------------------------------------------
// init: zero counts; block 0 / warp 0 also detects index dtype.
// (int32 data read as int64 has a random hi-word -> value outside [0,N_SEG);
//  misdetect prob ~ (2e-5)^32.)
// ---------------------------------------------------------------------------
__global__ void k_init(const void* __restrict__ idxp) {
    int t = blockIdx.x * blockDim.x + threadIdx.x;
    if (t < N_SEG) g_counts[t] = 0;
    if (blockIdx.x == 0 && threadIdx.x < 32) {
        long long v = ((const long long*)idxp)[threadIdx.x];
        unsigned ok = __ballot_sync(0xFFFFFFFFu, v >= 0 && v < (long long)N_SEG);
        if (threadIdx.x == 0) g_is64 = (ok == 0xFFFFFFFFu) ? 1 : 0;
    }
}

// ---------------------------------------------------------------------------
// histogram of segment ids (800K int atomics over 50K bins — cheap)
// ---------------------------------------------------------------------------
__global__ void __launch_bounds__(256) k_hist(const void* __restrict__ idxp, int E) {
    int e = blockIdx.x * blockDim.x + threadIdx.x;
    if (e >= E) return;
    atomicAdd(&g_counts[load_idx(idxp, e, g_is64)], 1);
}

// ---------------------------------------------------------------------------
// scan phase A: coalesced block-local exclusive scan (Hillis-Steele in smem),
// per-block totals to g_bsum.
// ---------------------------------------------------------------------------
__global__ void __launch_bounds__(SCAN_T) k_scanA() {
    __shared__ int s[SCAN_T];
    int t   = threadIdx.x;
    int gid = blockIdx.x * SCAN_T + t;
    int v   = (gid < N_SEG) ? g_counts[gid] : 0;
    s[t] = v;
    __syncthreads();
    #pragma unroll
    for (int off = 1; off < SCAN_T; off <<= 1) {
        int u = (t >= off) ? s[t - off] : 0;
        __syncthreads();
        s[t] += u;
        __syncthreads();
    }
    if (gid < N_SEG) g_offsets[gid] = s[t] - v;      // exclusive, block-local
    if (t == SCAN_T - 1) g_bsum[blockIdx.x] = s[t];  // block total
}

// ---------------------------------------------------------------------------
// scan phase B: exclusive scan of the 49 block sums (load coalesced -> smem,
// serial scan in smem by one thread, store coalesced).
// ---------------------------------------------------------------------------
__global__ void k_scanB() {
    __shared__ int s[SCAN_B];
    int t = threadIdx.x;
    if (t < SCAN_B) s[t] = g_bsum[t];
    __syncthreads();
    if (t == 0) {
        int run = 0;
        for (int b = 0; b < SCAN_B; b++) { int x = s[b]; s[b] = run; run += x; }
    }
    __syncthreads();
    if (t < SCAN_B) g_bsum[t] = s[t];
}

// ---------------------------------------------------------------------------
// scan phase C: add block offsets; init g_pos cursors; close the offsets array.
// ---------------------------------------------------------------------------
__global__ void __launch_bounds__(SCAN_T) k_scanC(int E) {
    int gid = blockIdx.x * SCAN_T + threadIdx.x;
    if (gid < N_SEG) {
        int off = g_offsets[gid] + g_bsum[gid >> 10];
        g_offsets[gid] = off;
        g_pos[gid]     = off;
    }
    if (gid == 0) g_offsets[N_SEG] = E;
}

// ---------------------------------------------------------------------------
// build permutation (slot order = atomic race order; fp-sum order tolerance
// is covered by rel_err threshold)
// ---------------------------------------------------------------------------
__global__ void __launch_bounds__(256) k_permute(const void* __restrict__ idxp, int E) {
    int e = blockIdx.x * blockDim.x + threadIdx.x;
    if (e >= E) return;
    int idx = load_idx(idxp, e, g_is64);
    int p = atomicAdd(&g_pos[idx], 1);
    g_perm[p] = e;
}

// ---------------------------------------------------------------------------
// gather-reduce: one warp per segment; lane owns a float2 column pair, so each
// row load is 32 x 8B = 256B fully coalesced. Unroll 8 for MLP (2KB in flight
// per warp). Writes the normalized mean directly.
// ---------------------------------------------------------------------------
__global__ void __launch_bounds__(256) k_reduce(const float2* __restrict__ src2,
                                                float2* __restrict__ out2,
                                                int n_seg) {
    int warp = (blockIdx.x * blockDim.x + threadIdx.x) >> 5;
    int lane = threadIdx.x & 31;
    if (warp >= n_seg) return;

    int start = g_offsets[warp];
    int end   = g_offsets[warp + 1];
    int count = end - start;

    float2 a0 = {0.f,0.f}, a1 = {0.f,0.f}, a2 = {0.f,0.f}, a3 = {0.f,0.f};

    int r = start;
    for (; r + 8 <= end; r += 8) {
        int e0 = g_perm[r+0], e1 = g_perm[r+1], e2 = g_perm[r+2], e3 = g_perm[r+3];
        int e4 = g_perm[r+4], e5 = g_perm[r+5], e6 = g_perm[r+6], e7 = g_perm[r+7];
        float2 v0 = __ldg(&src2[e0*32 + lane]);
        float2 v1 = __ldg(&src2[e1*32 + lane]);
        float2 v2 = __ldg(&src2[e2*32 + lane]);
        float2 v3 = __ldg(&src2[e3*32 + lane]);
        float2 v4 = __ldg(&src2[e4*32 + lane]);
        float2 v5 = __ldg(&src2[e5*32 + lane]);
        float2 v6 = __ldg(&src2[e6*32 + lane]);
        float2 v7 = __ldg(&src2[e7*32 + lane]);
        a0.x += v0.x + v4.x;  a0.y += v0.y + v4.y;
        a1.x += v1.x + v5.x;  a1.y += v1.y + v5.y;
        a2.x += v2.x + v6.x;  a2.y += v2.y + v6.y;
        a3.x += v3.x + v7.x;  a3.y += v3.y + v7.y;
    }
    for (; r + 2 <= end; r += 2) {
        int e0 = g_perm[r], e1 = g_perm[r+1];
        float2 v0 = __ldg(&src2[e0*32 + lane]);
        float2 v1 = __ldg(&src2[e1*32 + lane]);
        a0.x += v0.x; a0.y += v0.y;
        a1.x += v1.x; a1.y += v1.y;
    }
    if (r < end) {
        int e = g_perm[r];
        float2 v = __ldg(&src2[e*32 + lane]);
        a0.x += v.x; a0.y += v.y;
    }

    float sx = (a0.x + a1.x) + (a2.x + a3.x);
    float sy = (a0.y + a1.y) + (a2.y + a3.y);
    float inv = 1.0f / (float)max(count, 1);

    float2 o; o.x = sx * inv; o.y = sy * inv;
    out2[warp*32 + lane] = o;
}

// ---------------------------------------------------------------------------
extern "C" void kernel_launch(void* const* d_in, const int* in_sizes, int n_in,
                              void* d_out, int out_size) {
    const float* src  = (const float*)d_in[0];
    const void*  idxp = d_in[1];

    const int E     = in_sizes[0] / D_DIM;   // 800000
    const int rowsN = out_size / D_DIM;      // 50000

    k_init   <<<(N_SEG + 255) / 256, 256>>>(idxp);
    k_hist   <<<(E + 255) / 256, 256>>>(idxp, E);
    k_scanA  <<<SCAN_B, SCAN_T>>>();
    k_scanB  <<<1, 64>>>();
    k_scanC  <<<SCAN_B, SCAN_T>>>(E);
    k_permute<<<(E + 255) / 256, 256>>>(idxp, E);

    int blocks = (rowsN * 32 + 255) / 256;   // one warp per segment
    k_reduce <<<blocks, 256>>>((const float2*)src, (float2*)d_out, rowsN);
}